// round 6
// baseline (speedup 1.0000x reference)
#include <cuda_runtime.h>
#include <math.h>
#include <stdint.h>

#define NN 50000
#define NE 600000
#define IN_DIM 512
#define HIDDEN 128
#define OUT_DIM 64
#define N_LAYERS 3
#define EPS 0.1f

// ---------------- scratch (static device globals; no allocation) ----------------
__device__ int   g_cnt[NN];
__device__ int   g_off[NN + 4];
__device__ float g_dinv[NN];
__device__ int   g_csr_src[NE];
__device__ float g_norm[NE];
__device__ float g_alA[NN];
__device__ float g_arA[NN];
__device__ float g_alB[NN];
__device__ float g_arB[NN];
__device__ float g_raw[(size_t)NN * HIDDEN];
__device__ float g_hA[(size_t)NN * HIDDEN];
__device__ float g_hB[(size_t)NN * HIDDEN];

// ---------------- packed f32x2 helpers ----------------
__device__ __forceinline__ void fma_x2(unsigned long long& d, unsigned long long a,
                                       unsigned long long b) {
    asm("fma.rn.f32x2 %0, %1, %2, %3;" : "=l"(d) : "l"(a), "l"(b), "l"(d));
}
__device__ __forceinline__ float2 up64(unsigned long long v) {
    float2 f;
    asm("mov.b64 {%0, %1}, %2;" : "=f"(f.x), "=f"(f.y) : "l"(v));
    return f;
}

// ---------------- CSR build ----------------
__global__ void k_zero_cnt() {
    int i = blockIdx.x * blockDim.x + threadIdx.x;
    if (i < NN) g_cnt[i] = 0;
}

__global__ void k_count(const int* __restrict__ dst, int E) {
    int e = blockIdx.x * blockDim.x + threadIdx.x;
    if (e < E) atomicAdd(&g_cnt[dst[e]], 1);
}

__global__ __launch_bounds__(1024) void k_scan() {
    __shared__ int sh_warp[32];
    __shared__ int sh_carry;
    const int tid = threadIdx.x, lane = tid & 31, wid = tid >> 5;
    if (tid == 0) sh_carry = 0;
    __syncthreads();
    for (int base = 0; base < NN; base += 4096) {
        int idx = base + tid * 4;
        int4 c = make_int4(0, 0, 0, 0);
        if (idx < NN) c = *(const int4*)&g_cnt[idx];
        int t = c.x + c.y + c.z + c.w;
        int v = t;
#pragma unroll
        for (int o = 1; o < 32; o <<= 1) {
            int tt = __shfl_up_sync(0xffffffffu, v, o);
            if (lane >= o) v += tt;
        }
        if (lane == 31) sh_warp[wid] = v;
        __syncthreads();
        if (wid == 0) {
            int s = sh_warp[lane];
#pragma unroll
            for (int o = 1; o < 32; o <<= 1) {
                int tt = __shfl_up_sync(0xffffffffu, s, o);
                if (lane >= o) s += tt;
            }
            sh_warp[lane] = s;
        }
        __syncthreads();
        int warpoff = (wid > 0) ? sh_warp[wid - 1] : 0;
        int incl = v + warpoff;
        int excl = incl - t + sh_carry;
        if (idx < NN) {
            int4 off;
            off.x = excl;
            off.y = off.x + c.x;
            off.z = off.y + c.y;
            off.w = off.z + c.z;
            *(int4*)&g_off[idx] = off;
            float4 dv;
            dv.x = c.x ? rsqrtf((float)c.x) : 0.f;
            dv.y = c.y ? rsqrtf((float)c.y) : 0.f;
            dv.z = c.z ? rsqrtf((float)c.z) : 0.f;
            dv.w = c.w ? rsqrtf((float)c.w) : 0.f;
            *(float4*)&g_dinv[idx] = dv;
            *(int4*)&g_cnt[idx] = make_int4(0, 0, 0, 0);
        }
        __syncthreads();
        if (tid == 1023) sh_carry += incl;
        __syncthreads();
    }
    if (tid == 0) g_off[NN] = sh_carry;
}

__global__ void k_fill(const int* __restrict__ src, const int* __restrict__ dst, int E) {
    int e = blockIdx.x * blockDim.x + threadIdx.x;
    if (e < E) {
        int s = src[e], d = dst[e];
        int pos = g_off[d] + atomicAdd(&g_cnt[d], 1);
        g_csr_src[pos] = s;
        g_norm[pos] = g_dinv[s] * g_dinv[d];
    }
}

// ---------------- GEMM1: fma.rn.f32x2 inner loop, double-buffered smem ----------------
// acc[ip][j] packs rows (tm+2ip, tm+2ip+1) for column tn+j in one 64-bit reg.
__global__ __launch_bounds__(256, 2) void k_gemm1(const float* __restrict__ X,
                                                  const float* __restrict__ W,
                                                  const float* __restrict__ B,
                                                  const float* __restrict__ attL,
                                                  const float* __restrict__ attR,
                                                  float* __restrict__ al_out,
                                                  float* __restrict__ ar_out,
                                                  float* __restrict__ O, int M) {
    __shared__ __align__(16) float As[2][8][128];
    __shared__ __align__(16) float Bs2[2][8][256];   // duplicated columns
    const int tid = threadIdx.x;
    const int m0 = blockIdx.x * 128;
    const int lr = tid >> 1;          // 0..127
    const int lk = (tid & 1) * 4;     // 0 or 4
    const int tm = (tid >> 4) * 8;    // row group (8 rows)
    const int tn = (tid & 15) * 8;    // col group (8 cols)

    int gm = m0 + lr;
    if (gm >= M) gm = M - 1;
    const float* xp = X + (size_t)gm * IN_DIM + lk;
    const float* wp = W + (size_t)lr * IN_DIM + lk;

    unsigned long long acc[4][8];
#pragma unroll
    for (int i = 0; i < 4; i++)
#pragma unroll
        for (int j = 0; j < 8; j++) acc[i][j] = 0ull;

    // prologue: tile 0 into buffer 0
    {
        float4 xa = *(const float4*)(xp);
        float4 wa = *(const float4*)(wp);
        As[0][lk + 0][lr] = xa.x; As[0][lk + 1][lr] = xa.y;
        As[0][lk + 2][lr] = xa.z; As[0][lk + 3][lr] = xa.w;
        *(float2*)&Bs2[0][lk + 0][2 * lr] = make_float2(wa.x, wa.x);
        *(float2*)&Bs2[0][lk + 1][2 * lr] = make_float2(wa.y, wa.y);
        *(float2*)&Bs2[0][lk + 2][2 * lr] = make_float2(wa.z, wa.z);
        *(float2*)&Bs2[0][lk + 3][2 * lr] = make_float2(wa.w, wa.w);
    }
    __syncthreads();

    int buf = 0;
    for (int k0 = 0; k0 < IN_DIM - 8; k0 += 8) {
        float4 xa = *(const float4*)(xp + k0 + 8);
        float4 wa = *(const float4*)(wp + k0 + 8);
#pragma unroll
        for (int kk = 0; kk < 8; kk++) {
            ulonglong2 a01 = *(const ulonglong2*)&As[buf][kk][tm];
            ulonglong2 a23 = *(const ulonglong2*)&As[buf][kk][tm + 4];
            ulonglong2 b01 = *(const ulonglong2*)&Bs2[buf][kk][2 * tn];
            ulonglong2 b23 = *(const ulonglong2*)&Bs2[buf][kk][2 * tn + 4];
            ulonglong2 b45 = *(const ulonglong2*)&Bs2[buf][kk][2 * tn + 8];
            ulonglong2 b67 = *(const ulonglong2*)&Bs2[buf][kk][2 * tn + 12];
            unsigned long long a[4] = {a01.x, a01.y, a23.x, a23.y};
            unsigned long long b[8] = {b01.x, b01.y, b23.x, b23.y,
                                       b45.x, b45.y, b67.x, b67.y};
#pragma unroll
            for (int i = 0; i < 4; i++)
#pragma unroll
                for (int j = 0; j < 8; j++) fma_x2(acc[i][j], a[i], b[j]);
        }
        int nb = buf ^ 1;
        As[nb][lk + 0][lr] = xa.x; As[nb][lk + 1][lr] = xa.y;
        As[nb][lk + 2][lr] = xa.z; As[nb][lk + 3][lr] = xa.w;
        *(float2*)&Bs2[nb][lk + 0][2 * lr] = make_float2(wa.x, wa.x);
        *(float2*)&Bs2[nb][lk + 1][2 * lr] = make_float2(wa.y, wa.y);
        *(float2*)&Bs2[nb][lk + 2][2 * lr] = make_float2(wa.z, wa.z);
        *(float2*)&Bs2[nb][lk + 3][2 * lr] = make_float2(wa.w, wa.w);
        __syncthreads();
        buf = nb;
    }
#pragma unroll
    for (int kk = 0; kk < 8; kk++) {
        ulonglong2 a01 = *(const ulonglong2*)&As[buf][kk][tm];
        ulonglong2 a23 = *(const ulonglong2*)&As[buf][kk][tm + 4];
        ulonglong2 b01 = *(const ulonglong2*)&Bs2[buf][kk][2 * tn];
        ulonglong2 b23 = *(const ulonglong2*)&Bs2[buf][kk][2 * tn + 4];
        ulonglong2 b45 = *(const ulonglong2*)&Bs2[buf][kk][2 * tn + 8];
        ulonglong2 b67 = *(const ulonglong2*)&Bs2[buf][kk][2 * tn + 12];
        unsigned long long a[4] = {a01.x, a01.y, a23.x, a23.y};
        unsigned long long b[8] = {b01.x, b01.y, b23.x, b23.y,
                                   b45.x, b45.y, b67.x, b67.y};
#pragma unroll
        for (int i = 0; i < 4; i++)
#pragma unroll
            for (int j = 0; j < 8; j++) fma_x2(acc[i][j], a[i], b[j]);
    }

    // epilogue: bias + relu + store + fused att-dot (layer 0)
    float bias[8], wl[8], wr[8];
#pragma unroll
    for (int j = 0; j < 8; j++) {
        bias[j] = B[tn + j];
        wl[j] = attL[tn + j];
        wr[j] = attR[tn + j];
    }
#pragma unroll
    for (int i = 0; i < 8; i++) {
        int m = m0 + tm + i;
        float v[8];
#pragma unroll
        for (int j = 0; j < 8; j++) {
            float2 p = up64(acc[i >> 1][j]);
            float av = (i & 1) ? p.y : p.x;
            v[j] = fmaxf(av + bias[j], 0.f);
        }
        float sl = 0.f, sr = 0.f;
#pragma unroll
        for (int j = 0; j < 8; j++) {
            sl = fmaf(v[j], wl[j], sl);
            sr = fmaf(v[j], wr[j], sr);
        }
#pragma unroll
        for (int o = 8; o > 0; o >>= 1) {
            sl += __shfl_xor_sync(0xffffffffu, sl, o);
            sr += __shfl_xor_sync(0xffffffffu, sr, o);
        }
        if (m < M) {
            *(float4*)(O + (size_t)m * HIDDEN + tn) = make_float4(v[0], v[1], v[2], v[3]);
            *(float4*)(O + (size_t)m * HIDDEN + tn + 4) = make_float4(v[4], v[5], v[6], v[7]);
            if ((tid & 15) == 0) { al_out[m] = sl; ar_out[m] = sr; }
        }
    }
}

// ---------------- aggregation: warp-per-node CSR gather, fused coef + next-layer att ----------------
__global__ __launch_bounds__(256) void k_gather(const float4* __restrict__ h4,
                                                const float4* __restrict__ raw4,
                                                float4* __restrict__ o4,
                                                const float* __restrict__ al_in,
                                                const float* __restrict__ ar_in,
                                                const float4* __restrict__ attl_next,
                                                const float4* __restrict__ attr_next,
                                                float* __restrict__ al_out,
                                                float* __restrict__ ar_out,
                                                int M) {
    int w = (blockIdx.x * blockDim.x + threadIdx.x) >> 5;
    int lane = threadIdx.x & 31;
    if (w >= M) return;
    int b = g_off[w];
    int e = g_off[w + 1];
    float ar_w = ar_in[w];
    float4 r = raw4[(size_t)w * 32 + lane];
    float4 acc;
    acc.x = EPS * r.x; acc.y = EPS * r.y; acc.z = EPS * r.z; acc.w = EPS * r.w;

    for (int j0 = b; j0 < e; j0 += 32) {
        int jj = j0 + lane;
        float cl = 0.f;
        int sl = 0;
        if (jj < e) {
            sl = __ldg(&g_csr_src[jj]);
            float nrm = __ldg(&g_norm[jj]);
            cl = tanhf(al_in[sl] + ar_w) * nrm;
        }
        int cnt = min(32, e - j0);
        for (int k = 0; k < cnt; k++) {
            float c = __shfl_sync(0xffffffffu, cl, k);
            int s = __shfl_sync(0xffffffffu, sl, k);
            float4 v = h4[(size_t)s * 32 + lane];
            acc.x = fmaf(c, v.x, acc.x);
            acc.y = fmaf(c, v.y, acc.y);
            acc.z = fmaf(c, v.z, acc.z);
            acc.w = fmaf(c, v.w, acc.w);
        }
    }
    o4[(size_t)w * 32 + lane] = acc;

    if (attl_next) {
        float4 wl = attl_next[lane];
        float4 wr = attr_next[lane];
        float a = acc.x * wl.x + acc.y * wl.y + acc.z * wl.z + acc.w * wl.w;
        float bb = acc.x * wr.x + acc.y * wr.y + acc.z * wr.z + acc.w * wr.w;
#pragma unroll
        for (int o = 16; o > 0; o >>= 1) {
            a += __shfl_xor_sync(0xffffffffu, a, o);
            bb += __shfl_xor_sync(0xffffffffu, bb, o);
        }
        if (lane == 0) { al_out[w] = a; ar_out[w] = bb; }
    }
}

// ---------------- GEMM2 + fused log_softmax ----------------
__global__ __launch_bounds__(256) void k_gemm2(const float* __restrict__ H,
                                               const float* __restrict__ W,
                                               const float* __restrict__ B,
                                               float* __restrict__ Emb,
                                               float* __restrict__ Ls, int M) {
    __shared__ float As[16][64];
    __shared__ float Bs[16][64];
    const int tid = threadIdx.x;
    const int m0 = blockIdx.x * 64;
    const int lr = tid >> 2;
    const int lk = (tid & 3) * 4;
    const int tm = (tid >> 4) * 4;
    const int tn = (tid & 15) * 4;

    int gm = m0 + lr;
    if (gm >= M) gm = M - 1;
    const float* hp = H + (size_t)gm * HIDDEN + lk;
    const float* wp = W + (size_t)lr * HIDDEN + lk;

    float acc[4][4];
#pragma unroll
    for (int i = 0; i < 4; i++)
#pragma unroll
        for (int j = 0; j < 4; j++) acc[i][j] = 0.f;

    for (int k0 = 0; k0 < HIDDEN; k0 += 16) {
        float4 xa = *(const float4*)(hp + k0);
        float4 wa = *(const float4*)(wp + k0);
        As[lk + 0][lr] = xa.x; As[lk + 1][lr] = xa.y;
        As[lk + 2][lr] = xa.z; As[lk + 3][lr] = xa.w;
        Bs[lk + 0][lr] = wa.x; Bs[lk + 1][lr] = wa.y;
        Bs[lk + 2][lr] = wa.z; Bs[lk + 3][lr] = wa.w;
        __syncthreads();
#pragma unroll
        for (int kk = 0; kk < 16; kk++) {
            float4 a4 = *(const float4*)&As[kk][tm];
            float4 b4 = *(const float4*)&Bs[kk][tn];
            float a[4] = {a4.x, a4.y, a4.z, a4.w};
            float b[4] = {b4.x, b4.y, b4.z, b4.w};
#pragma unroll
            for (int i = 0; i < 4; i++)
#pragma unroll
                for (int j = 0; j < 4; j++) acc[i][j] = fmaf(a[i], b[j], acc[i][j]);
        }
        __syncthreads();
    }

    float bias[4];
#pragma unroll
    for (int j = 0; j < 4; j++) bias[j] = B[tn + j];

#pragma unroll
    for (int i = 0; i < 4; i++) {
        int m = m0 + tm + i;
        float v[4];
#pragma unroll
        for (int j = 0; j < 4; j++) v[j] = acc[i][j] + bias[j];
        float mx = fmaxf(fmaxf(v[0], v[1]), fmaxf(v[2], v[3]));
#pragma unroll
        for (int o = 8; o > 0; o >>= 1) mx = fmaxf(mx, __shfl_xor_sync(0xffffffffu, mx, o));
        float s = expf(v[0] - mx) + expf(v[1] - mx) + expf(v[2] - mx) + expf(v[3] - mx);
#pragma unroll
        for (int o = 8; o > 0; o >>= 1) s += __shfl_xor_sync(0xffffffffu, s, o);
        float lse = mx + logf(s);
        if (m < M) {
            float4 ev = make_float4(v[0], v[1], v[2], v[3]);
            float4 lv = make_float4(v[0] - lse, v[1] - lse, v[2] - lse, v[3] - lse);
            *(float4*)(Emb + (size_t)m * OUT_DIM + tn) = ev;
            *(float4*)(Ls + (size_t)m * OUT_DIM + tn) = lv;
        }
    }
}

// ---------------- launch ----------------
extern "C" void kernel_launch(void* const* d_in, const int* in_sizes, int n_in,
                              void* d_out, int out_size) {
    const float* x    = (const float*)d_in[0];
    const int*   ei   = (const int*)  d_in[1];
    const float* t1w  = (const float*)d_in[2];
    const float* t1b  = (const float*)d_in[3];
    const float* t2w  = (const float*)d_in[4];
    const float* t2b  = (const float*)d_in[5];
    const float* attl = (const float*)d_in[6];
    const float* attr = (const float*)d_in[7];

    const int M = in_sizes[0] / IN_DIM;   // 50000
    const int E = in_sizes[1] / 2;        // 600000
    const int* src = ei;
    const int* dst = ei + E;

    float *raw, *hA, *hB, *alA, *arA, *alB, *arB;
    cudaGetSymbolAddress((void**)&raw, g_raw);
    cudaGetSymbolAddress((void**)&hA, g_hA);
    cudaGetSymbolAddress((void**)&hB, g_hB);
    cudaGetSymbolAddress((void**)&alA, g_alA);
    cudaGetSymbolAddress((void**)&arA, g_arA);
    cudaGetSymbolAddress((void**)&alB, g_alB);
    cudaGetSymbolAddress((void**)&arB, g_arB);

    float* out_ls  = (float*)d_out;
    float* out_emb = out_ls + (size_t)M * OUT_DIM;

    // CSR build
    k_zero_cnt<<<(NN + 255) / 256, 256>>>();
    k_count<<<(E + 255) / 256, 256>>>(dst, E);
    k_scan<<<1, 1024>>>();
    k_fill<<<(E + 255) / 256, 256>>>(src, dst, E);

    // h = relu(x @ t1_w^T + b) -> raw; fused att dots (layer 0) -> buffers A
    k_gemm1<<<(M + 127) / 128, 256>>>(x, t1w, t1b, attl, attr, alA, arA, raw, M);

    const float* cur = raw;
    float* nxt = hA;
    for (int l = 0; l < N_LAYERS; l++) {
        const float* anl = (l + 1 < N_LAYERS) ? (attl + (l + 1) * HIDDEN) : nullptr;
        const float* anr = (l + 1 < N_LAYERS) ? (attr + (l + 1) * HIDDEN) : nullptr;
        const float* al_in = (l & 1) ? alB : alA;
        const float* ar_in = (l & 1) ? arB : arA;
        float* al_out = (l & 1) ? alA : alB;
        float* ar_out = (l & 1) ? arA : arB;
        k_gather<<<((size_t)M * 32 + 255) / 256, 256>>>((const float4*)cur,
                                                        (const float4*)raw,
                                                        (float4*)nxt,
                                                        al_in, ar_in,
                                                        (const float4*)anl,
                                                        (const float4*)anr,
                                                        al_out, ar_out, M);
        cur = nxt;
        nxt = (cur == hA) ? hB : hA;
    }

    k_gemm2<<<(M + 63) / 64, 256>>>(cur, t2w, t2b, out_emb, out_ls, M);
}

// round 7
// speedup vs baseline: 1.7479x; 1.7479x over previous
#include <cuda_runtime.h>
#include <math.h>
#include <stdint.h>

#define NN 50000
#define NE 600000
#define IN_DIM 512
#define HIDDEN 128
#define OUT_DIM 64
#define N_LAYERS 3
#define EPS 0.1f

// ---------------- scratch (static device globals; no allocation) ----------------
__device__ int   g_cnt[NN];
__device__ int   g_off[NN + 4];
__device__ float g_dinv[NN];
__device__ int   g_csr_src[NE];
__device__ float g_norm[NE];
__device__ float g_alA[NN];
__device__ float g_arA[NN];
__device__ float g_alB[NN];
__device__ float g_arB[NN];
__device__ float g_raw[(size_t)NN * HIDDEN];
__device__ float g_hA[(size_t)NN * HIDDEN];
__device__ float g_hB[(size_t)NN * HIDDEN];

// ---------------- CSR build ----------------
__global__ void k_zero_cnt() {
    int i = blockIdx.x * blockDim.x + threadIdx.x;
    if (i < NN) g_cnt[i] = 0;
}

__global__ void k_count(const int* __restrict__ dst, int E) {
    int e = blockIdx.x * blockDim.x + threadIdx.x;
    if (e < E) atomicAdd(&g_cnt[dst[e]], 1);
}

__global__ __launch_bounds__(1024) void k_scan() {
    __shared__ int sh_warp[32];
    __shared__ int sh_carry;
    const int tid = threadIdx.x, lane = tid & 31, wid = tid >> 5;
    if (tid == 0) sh_carry = 0;
    __syncthreads();
    for (int base = 0; base < NN; base += 4096) {
        int idx = base + tid * 4;
        int4 c = make_int4(0, 0, 0, 0);
        if (idx < NN) c = *(const int4*)&g_cnt[idx];
        int t = c.x + c.y + c.z + c.w;
        int v = t;
#pragma unroll
        for (int o = 1; o < 32; o <<= 1) {
            int tt = __shfl_up_sync(0xffffffffu, v, o);
            if (lane >= o) v += tt;
        }
        if (lane == 31) sh_warp[wid] = v;
        __syncthreads();
        if (wid == 0) {
            int s = sh_warp[lane];
#pragma unroll
            for (int o = 1; o < 32; o <<= 1) {
                int tt = __shfl_up_sync(0xffffffffu, s, o);
                if (lane >= o) s += tt;
            }
            sh_warp[lane] = s;
        }
        __syncthreads();
        int warpoff = (wid > 0) ? sh_warp[wid - 1] : 0;
        int incl = v + warpoff;
        int excl = incl - t + sh_carry;
        if (idx < NN) {
            int4 off;
            off.x = excl;
            off.y = off.x + c.x;
            off.z = off.y + c.y;
            off.w = off.z + c.z;
            *(int4*)&g_off[idx] = off;
            float4 dv;
            dv.x = c.x ? rsqrtf((float)c.x) : 0.f;
            dv.y = c.y ? rsqrtf((float)c.y) : 0.f;
            dv.z = c.z ? rsqrtf((float)c.z) : 0.f;
            dv.w = c.w ? rsqrtf((float)c.w) : 0.f;
            *(float4*)&g_dinv[idx] = dv;
            *(int4*)&g_cnt[idx] = make_int4(0, 0, 0, 0);
        }
        __syncthreads();
        if (tid == 1023) sh_carry += incl;
        __syncthreads();
    }
    if (tid == 0) g_off[NN] = sh_carry;
}

__global__ void k_fill(const int* __restrict__ src, const int* __restrict__ dst, int E) {
    int e = blockIdx.x * blockDim.x + threadIdx.x;
    if (e < E) {
        int s = src[e], d = dst[e];
        int pos = g_off[d] + atomicAdd(&g_cnt[d], 1);
        g_csr_src[pos] = s;
        g_norm[pos] = g_dinv[s] * g_dinv[d];
    }
}

// ---------------- GEMM1 (R4 version: double-buffered fp32 FFMA) + fused att ----------------
__global__ __launch_bounds__(256, 2) void k_gemm1(const float* __restrict__ X,
                                                  const float* __restrict__ W,
                                                  const float* __restrict__ B,
                                                  const float* __restrict__ attL,
                                                  const float* __restrict__ attR,
                                                  float* __restrict__ al_out,
                                                  float* __restrict__ ar_out,
                                                  float* __restrict__ O, int M) {
    __shared__ float As[2][8][128];
    __shared__ float Bs[2][8][128];
    const int tid = threadIdx.x;
    const int m0 = blockIdx.x * 128;
    const int lr = tid >> 1;
    const int lk = (tid & 1) * 4;
    const int tm = (tid >> 4) * 8;
    const int tn = (tid & 15) * 8;

    int gm = m0 + lr;
    if (gm >= M) gm = M - 1;
    const float* xp = X + (size_t)gm * IN_DIM + lk;
    const float* wp = W + (size_t)lr * IN_DIM + lk;

    float acc[8][8];
#pragma unroll
    for (int i = 0; i < 8; i++)
#pragma unroll
        for (int j = 0; j < 8; j++) acc[i][j] = 0.f;

    {
        float4 xa = *(const float4*)(xp);
        float4 wa = *(const float4*)(wp);
        As[0][lk + 0][lr] = xa.x; As[0][lk + 1][lr] = xa.y;
        As[0][lk + 2][lr] = xa.z; As[0][lk + 3][lr] = xa.w;
        Bs[0][lk + 0][lr] = wa.x; Bs[0][lk + 1][lr] = wa.y;
        Bs[0][lk + 2][lr] = wa.z; Bs[0][lk + 3][lr] = wa.w;
    }
    __syncthreads();

    int buf = 0;
    for (int k0 = 0; k0 < IN_DIM - 8; k0 += 8) {
        float4 xa = *(const float4*)(xp + k0 + 8);
        float4 wa = *(const float4*)(wp + k0 + 8);
#pragma unroll
        for (int kk = 0; kk < 8; kk++) {
            float4 a0 = *(const float4*)&As[buf][kk][tm];
            float4 a1 = *(const float4*)&As[buf][kk][tm + 4];
            float4 b0 = *(const float4*)&Bs[buf][kk][tn];
            float4 b1 = *(const float4*)&Bs[buf][kk][tn + 4];
            float a[8] = {a0.x, a0.y, a0.z, a0.w, a1.x, a1.y, a1.z, a1.w};
            float b[8] = {b0.x, b0.y, b0.z, b0.w, b1.x, b1.y, b1.z, b1.w};
#pragma unroll
            for (int i = 0; i < 8; i++)
#pragma unroll
                for (int j = 0; j < 8; j++) acc[i][j] = fmaf(a[i], b[j], acc[i][j]);
        }
        int nb = buf ^ 1;
        As[nb][lk + 0][lr] = xa.x; As[nb][lk + 1][lr] = xa.y;
        As[nb][lk + 2][lr] = xa.z; As[nb][lk + 3][lr] = xa.w;
        Bs[nb][lk + 0][lr] = wa.x; Bs[nb][lk + 1][lr] = wa.y;
        Bs[nb][lk + 2][lr] = wa.z; Bs[nb][lk + 3][lr] = wa.w;
        __syncthreads();
        buf = nb;
    }
#pragma unroll
    for (int kk = 0; kk < 8; kk++) {
        float4 a0 = *(const float4*)&As[buf][kk][tm];
        float4 a1 = *(const float4*)&As[buf][kk][tm + 4];
        float4 b0 = *(const float4*)&Bs[buf][kk][tn];
        float4 b1 = *(const float4*)&Bs[buf][kk][tn + 4];
        float a[8] = {a0.x, a0.y, a0.z, a0.w, a1.x, a1.y, a1.z, a1.w};
        float b[8] = {b0.x, b0.y, b0.z, b0.w, b1.x, b1.y, b1.z, b1.w};
#pragma unroll
        for (int i = 0; i < 8; i++)
#pragma unroll
            for (int j = 0; j < 8; j++) acc[i][j] = fmaf(a[i], b[j], acc[i][j]);
    }

    float bias[8], wl[8], wr[8];
#pragma unroll
    for (int j = 0; j < 8; j++) {
        bias[j] = B[tn + j];
        wl[j] = attL[tn + j];
        wr[j] = attR[tn + j];
    }
#pragma unroll
    for (int i = 0; i < 8; i++) {
        int m = m0 + tm + i;
        float v[8];
#pragma unroll
        for (int j = 0; j < 8; j++) v[j] = fmaxf(acc[i][j] + bias[j], 0.f);
        float sl = 0.f, sr = 0.f;
#pragma unroll
        for (int j = 0; j < 8; j++) {
            sl = fmaf(v[j], wl[j], sl);
            sr = fmaf(v[j], wr[j], sr);
        }
#pragma unroll
        for (int o = 8; o > 0; o >>= 1) {
            sl += __shfl_xor_sync(0xffffffffu, sl, o);
            sr += __shfl_xor_sync(0xffffffffu, sr, o);
        }
        if (m < M) {
            *(float4*)(O + (size_t)m * HIDDEN + tn) = make_float4(v[0], v[1], v[2], v[3]);
            *(float4*)(O + (size_t)m * HIDDEN + tn + 4) = make_float4(v[4], v[5], v[6], v[7]);
            if ((tid & 15) == 0) { al_out[m] = sl; ar_out[m] = sr; }
        }
    }
}

// ---------------- aggregation: warp-per-node CSR gather, 4-way unrolled (MLP=4) ----------------
__global__ __launch_bounds__(256) void k_gather(const float4* __restrict__ h4,
                                                const float4* __restrict__ raw4,
                                                float4* __restrict__ o4,
                                                const float* __restrict__ al_in,
                                                const float* __restrict__ ar_in,
                                                const float4* __restrict__ attl_next,
                                                const float4* __restrict__ attr_next,
                                                float* __restrict__ al_out,
                                                float* __restrict__ ar_out,
                                                int M) {
    int w = (blockIdx.x * blockDim.x + threadIdx.x) >> 5;
    int lane = threadIdx.x & 31;
    if (w >= M) return;
    int b = g_off[w];
    int e = g_off[w + 1];
    float ar_w = ar_in[w];
    float4 r = raw4[(size_t)w * 32 + lane];
    float4 acc0 = make_float4(EPS * r.x, EPS * r.y, EPS * r.z, EPS * r.w);
    float4 acc1 = make_float4(0.f, 0.f, 0.f, 0.f);
    float4 acc2 = make_float4(0.f, 0.f, 0.f, 0.f);
    float4 acc3 = make_float4(0.f, 0.f, 0.f, 0.f);

    for (int j0 = b; j0 < e; j0 += 32) {
        int jj = j0 + lane;
        float cl = 0.f;
        int sl = 0;
        if (jj < e) {
            sl = __ldg(&g_csr_src[jj]);
            float nrm = __ldg(&g_norm[jj]);
            cl = tanhf(al_in[sl] + ar_w) * nrm;
        }
        int cnt = min(32, e - j0);
        int k = 0;
        for (; k + 4 <= cnt; k += 4) {
            float c0 = __shfl_sync(0xffffffffu, cl, k);
            float c1 = __shfl_sync(0xffffffffu, cl, k + 1);
            float c2 = __shfl_sync(0xffffffffu, cl, k + 2);
            float c3 = __shfl_sync(0xffffffffu, cl, k + 3);
            int s0 = __shfl_sync(0xffffffffu, sl, k);
            int s1 = __shfl_sync(0xffffffffu, sl, k + 1);
            int s2 = __shfl_sync(0xffffffffu, sl, k + 2);
            int s3 = __shfl_sync(0xffffffffu, sl, k + 3);
            float4 v0 = h4[(size_t)s0 * 32 + lane];
            float4 v1 = h4[(size_t)s1 * 32 + lane];
            float4 v2 = h4[(size_t)s2 * 32 + lane];
            float4 v3 = h4[(size_t)s3 * 32 + lane];
            acc0.x = fmaf(c0, v0.x, acc0.x); acc0.y = fmaf(c0, v0.y, acc0.y);
            acc0.z = fmaf(c0, v0.z, acc0.z); acc0.w = fmaf(c0, v0.w, acc0.w);
            acc1.x = fmaf(c1, v1.x, acc1.x); acc1.y = fmaf(c1, v1.y, acc1.y);
            acc1.z = fmaf(c1, v1.z, acc1.z); acc1.w = fmaf(c1, v1.w, acc1.w);
            acc2.x = fmaf(c2, v2.x, acc2.x); acc2.y = fmaf(c2, v2.y, acc2.y);
            acc2.z = fmaf(c2, v2.z, acc2.z); acc2.w = fmaf(c2, v2.w, acc2.w);
            acc3.x = fmaf(c3, v3.x, acc3.x); acc3.y = fmaf(c3, v3.y, acc3.y);
            acc3.z = fmaf(c3, v3.z, acc3.z); acc3.w = fmaf(c3, v3.w, acc3.w);
        }
        for (; k < cnt; k++) {
            float c = __shfl_sync(0xffffffffu, cl, k);
            int s = __shfl_sync(0xffffffffu, sl, k);
            float4 v = h4[(size_t)s * 32 + lane];
            acc0.x = fmaf(c, v.x, acc0.x); acc0.y = fmaf(c, v.y, acc0.y);
            acc0.z = fmaf(c, v.z, acc0.z); acc0.w = fmaf(c, v.w, acc0.w);
        }
    }
    float4 acc;
    acc.x = (acc0.x + acc1.x) + (acc2.x + acc3.x);
    acc.y = (acc0.y + acc1.y) + (acc2.y + acc3.y);
    acc.z = (acc0.z + acc1.z) + (acc2.z + acc3.z);
    acc.w = (acc0.w + acc1.w) + (acc2.w + acc3.w);
    o4[(size_t)w * 32 + lane] = acc;

    if (attl_next) {
        float4 wl = attl_next[lane];
        float4 wr = attr_next[lane];
        float a = acc.x * wl.x + acc.y * wl.y + acc.z * wl.z + acc.w * wl.w;
        float bb = acc.x * wr.x + acc.y * wr.y + acc.z * wr.z + acc.w * wr.w;
#pragma unroll
        for (int o = 16; o > 0; o >>= 1) {
            a += __shfl_xor_sync(0xffffffffu, a, o);
            bb += __shfl_xor_sync(0xffffffffu, bb, o);
        }
        if (lane == 0) { al_out[w] = a; ar_out[w] = bb; }
    }
}

// ---------------- GEMM2 + fused log_softmax ----------------
__global__ __launch_bounds__(256) void k_gemm2(const float* __restrict__ H,
                                               const float* __restrict__ W,
                                               const float* __restrict__ B,
                                               float* __restrict__ Emb,
                                               float* __restrict__ Ls, int M) {
    __shared__ float As[16][64];
    __shared__ float Bs[16][64];
    const int tid = threadIdx.x;
    const int m0 = blockIdx.x * 64;
    const int lr = tid >> 2;
    const int lk = (tid & 3) * 4;
    const int tm = (tid >> 4) * 4;
    const int tn = (tid & 15) * 4;

    int gm = m0 + lr;
    if (gm >= M) gm = M - 1;
    const float* hp = H + (size_t)gm * HIDDEN + lk;
    const float* wp = W + (size_t)lr * HIDDEN + lk;

    float acc[4][4];
#pragma unroll
    for (int i = 0; i < 4; i++)
#pragma unroll
        for (int j = 0; j < 4; j++) acc[i][j] = 0.f;

    for (int k0 = 0; k0 < HIDDEN; k0 += 16) {
        float4 xa = *(const float4*)(hp + k0);
        float4 wa = *(const float4*)(wp + k0);
        As[lk + 0][lr] = xa.x; As[lk + 1][lr] = xa.y;
        As[lk + 2][lr] = xa.z; As[lk + 3][lr] = xa.w;
        Bs[lk + 0][lr] = wa.x; Bs[lk + 1][lr] = wa.y;
        Bs[lk + 2][lr] = wa.z; Bs[lk + 3][lr] = wa.w;
        __syncthreads();
#pragma unroll
        for (int kk = 0; kk < 16; kk++) {
            float4 a4 = *(const float4*)&As[kk][tm];
            float4 b4 = *(const float4*)&Bs[kk][tn];
            float a[4] = {a4.x, a4.y, a4.z, a4.w};
            float b[4] = {b4.x, b4.y, b4.z, b4.w};
#pragma unroll
            for (int i = 0; i < 4; i++)
#pragma unroll
                for (int j = 0; j < 4; j++) acc[i][j] = fmaf(a[i], b[j], acc[i][j]);
        }
        __syncthreads();
    }

    float bias[4];
#pragma unroll
    for (int j = 0; j < 4; j++) bias[j] = B[tn + j];

#pragma unroll
    for (int i = 0; i < 4; i++) {
        int m = m0 + tm + i;
        float v[4];
#pragma unroll
        for (int j = 0; j < 4; j++) v[j] = acc[i][j] + bias[j];
        float mx = fmaxf(fmaxf(v[0], v[1]), fmaxf(v[2], v[3]));
#pragma unroll
        for (int o = 8; o > 0; o >>= 1) mx = fmaxf(mx, __shfl_xor_sync(0xffffffffu, mx, o));
        float s = expf(v[0] - mx) + expf(v[1] - mx) + expf(v[2] - mx) + expf(v[3] - mx);
#pragma unroll
        for (int o = 8; o > 0; o >>= 1) s += __shfl_xor_sync(0xffffffffu, s, o);
        float lse = mx + logf(s);
        if (m < M) {
            float4 ev = make_float4(v[0], v[1], v[2], v[3]);
            float4 lv = make_float4(v[0] - lse, v[1] - lse, v[2] - lse, v[3] - lse);
            *(float4*)(Emb + (size_t)m * OUT_DIM + tn) = ev;
            *(float4*)(Ls + (size_t)m * OUT_DIM + tn) = lv;
        }
    }
}

// ---------------- launch ----------------
extern "C" void kernel_launch(void* const* d_in, const int* in_sizes, int n_in,
                              void* d_out, int out_size) {
    const float* x    = (const float*)d_in[0];
    const int*   ei   = (const int*)  d_in[1];
    const float* t1w  = (const float*)d_in[2];
    const float* t1b  = (const float*)d_in[3];
    const float* t2w  = (const float*)d_in[4];
    const float* t2b  = (const float*)d_in[5];
    const float* attl = (const float*)d_in[6];
    const float* attr = (const float*)d_in[7];

    const int M = in_sizes[0] / IN_DIM;   // 50000
    const int E = in_sizes[1] / 2;        // 600000
    const int* src = ei;
    const int* dst = ei + E;

    float *raw, *hA, *hB, *alA, *arA, *alB, *arB;
    cudaGetSymbolAddress((void**)&raw, g_raw);
    cudaGetSymbolAddress((void**)&hA, g_hA);
    cudaGetSymbolAddress((void**)&hB, g_hB);
    cudaGetSymbolAddress((void**)&alA, g_alA);
    cudaGetSymbolAddress((void**)&arA, g_arA);
    cudaGetSymbolAddress((void**)&alB, g_alB);
    cudaGetSymbolAddress((void**)&arB, g_arB);

    float* out_ls  = (float*)d_out;
    float* out_emb = out_ls + (size_t)M * OUT_DIM;

    // one-time side-stream resources (created outside graph capture on first call)
    static cudaStream_t s2 = nullptr;
    static cudaEvent_t evFork = nullptr, evJoin = nullptr;
    if (!s2) {
        cudaStreamCreateWithFlags(&s2, cudaStreamNonBlocking);
        cudaEventCreateWithFlags(&evFork, cudaEventDisableTiming);
        cudaEventCreateWithFlags(&evJoin, cudaEventDisableTiming);
    }

    // fork: CSR build on s2, GEMM1 on default stream (independent work overlaps)
    cudaEventRecord(evFork, 0);
    cudaStreamWaitEvent(s2, evFork, 0);

    k_zero_cnt<<<(NN + 255) / 256, 256, 0, s2>>>();
    k_count<<<(E + 255) / 256, 256, 0, s2>>>(dst, E);
    k_scan<<<1, 1024, 0, s2>>>();
    k_fill<<<(E + 255) / 256, 256, 0, s2>>>(src, dst, E);
    cudaEventRecord(evJoin, s2);

    k_gemm1<<<(M + 127) / 128, 256>>>(x, t1w, t1b, attl, attr, alA, arA, raw, M);

    // join before the first gather needs CSR
    cudaStreamWaitEvent(0, evJoin, 0);

    const float* cur = raw;
    float* nxt = hA;
    for (int l = 0; l < N_LAYERS; l++) {
        const float* anl = (l + 1 < N_LAYERS) ? (attl + (l + 1) * HIDDEN) : nullptr;
        const float* anr = (l + 1 < N_LAYERS) ? (attr + (l + 1) * HIDDEN) : nullptr;
        const float* al_in = (l & 1) ? alB : alA;
        const float* ar_in = (l & 1) ? arB : arA;
        float* al_out = (l & 1) ? alA : alB;
        float* ar_out = (l & 1) ? arA : arB;
        k_gather<<<((size_t)M * 32 + 255) / 256, 256>>>((const float4*)cur,
                                                        (const float4*)raw,
                                                        (float4*)nxt,
                                                        al_in, ar_in,
                                                        (const float4*)anl,
                                                        (const float4*)anr,
                                                        al_out, ar_out, M);
        cur = nxt;
        nxt = (cur == hA) ? hB : hA;
    }

    k_gemm2<<<(M + 63) / 64, 256>>>(cur, t2w, t2b, out_emb, out_ls, M);
}

// round 8
// speedup vs baseline: 1.9048x; 1.0897x over previous
#include <cuda_runtime.h>
#include <cuda_bf16.h>
#include <math.h>
#include <stdint.h>

#define NN 50000
#define NE 600000
#define IN_DIM 512
#define HIDDEN 128
#define OUT_DIM 64
#define N_LAYERS 3
#define EPS 0.1f

// ---------------- scratch (static device globals; no allocation) ----------------
__device__ int   g_cnt[NN];
__device__ int   g_off[NN + 4];
__device__ float g_dinv[NN];
__device__ int   g_csr_src[NE];
__device__ float g_norm[NE];
__device__ float g_alA[NN];
__device__ float g_arA[NN];
__device__ float g_alB[NN];
__device__ float g_arB[NN];
__device__ float g_raw[(size_t)NN * HIDDEN];
__device__ float g_hA[(size_t)NN * HIDDEN];
__device__ float g_hB[(size_t)NN * HIDDEN];
__device__ __nv_bfloat16 g_wh[HIDDEN * IN_DIM];
__device__ __nv_bfloat16 g_wl[HIDDEN * IN_DIM];

// ---------------- CSR build ----------------
__global__ void k_zero_cnt() {
    int i = blockIdx.x * blockDim.x + threadIdx.x;
    if (i < NN) g_cnt[i] = 0;
}

__global__ void k_count(const int* __restrict__ dst, int E) {
    int e = blockIdx.x * blockDim.x + threadIdx.x;
    if (e < E) atomicAdd(&g_cnt[dst[e]], 1);
}

__global__ __launch_bounds__(1024) void k_scan() {
    __shared__ int sh_warp[32];
    __shared__ int sh_carry;
    const int tid = threadIdx.x, lane = tid & 31, wid = tid >> 5;
    if (tid == 0) sh_carry = 0;
    __syncthreads();
    for (int base = 0; base < NN; base += 4096) {
        int idx = base + tid * 4;
        int4 c = make_int4(0, 0, 0, 0);
        if (idx < NN) c = *(const int4*)&g_cnt[idx];
        int t = c.x + c.y + c.z + c.w;
        int v = t;
#pragma unroll
        for (int o = 1; o < 32; o <<= 1) {
            int tt = __shfl_up_sync(0xffffffffu, v, o);
            if (lane >= o) v += tt;
        }
        if (lane == 31) sh_warp[wid] = v;
        __syncthreads();
        if (wid == 0) {
            int s = sh_warp[lane];
#pragma unroll
            for (int o = 1; o < 32; o <<= 1) {
                int tt = __shfl_up_sync(0xffffffffu, s, o);
                if (lane >= o) s += tt;
            }
            sh_warp[lane] = s;
        }
        __syncthreads();
        int warpoff = (wid > 0) ? sh_warp[wid - 1] : 0;
        int incl = v + warpoff;
        int excl = incl - t + sh_carry;
        if (idx < NN) {
            int4 off;
            off.x = excl;
            off.y = off.x + c.x;
            off.z = off.y + c.y;
            off.w = off.z + c.z;
            *(int4*)&g_off[idx] = off;
            float4 dv;
            dv.x = c.x ? rsqrtf((float)c.x) : 0.f;
            dv.y = c.y ? rsqrtf((float)c.y) : 0.f;
            dv.z = c.z ? rsqrtf((float)c.z) : 0.f;
            dv.w = c.w ? rsqrtf((float)c.w) : 0.f;
            *(float4*)&g_dinv[idx] = dv;
            *(int4*)&g_cnt[idx] = make_int4(0, 0, 0, 0);
        }
        __syncthreads();
        if (tid == 1023) sh_carry += incl;
        __syncthreads();
    }
    if (tid == 0) g_off[NN] = sh_carry;
}

__global__ void k_fill(const int* __restrict__ src, const int* __restrict__ dst, int E) {
    int e = blockIdx.x * blockDim.x + threadIdx.x;
    if (e < E) {
        int s = src[e], d = dst[e];
        int pos = g_off[d] + atomicAdd(&g_cnt[d], 1);
        g_csr_src[pos] = s;
        g_norm[pos] = g_dinv[s] * g_dinv[d];
    }
}

// ---------------- W split to bf16 hi/lo ----------------
__global__ void k_wconv(const float* __restrict__ W) {
    int i = blockIdx.x * blockDim.x + threadIdx.x;
    if (i < HIDDEN * IN_DIM) {
        float w = W[i];
        __nv_bfloat16 h = __float2bfloat16_rn(w);
        g_wh[i] = h;
        g_wl[i] = __float2bfloat16_rn(w - __bfloat162float(h));
    }
}

// ---------------- GEMM1 via mma.sync bf16-split + fused bias/relu/att ----------------
// Block: 256 thr (8 warps). Tile: M=128, N=128(full), K chunks of 64.
// smem: A and W staged as (row, kpair)->uint2{hi_pair, lo_pair}, pitch 33 uint2.
#define APITCH 33
#define CHUNK_UINT2 (128 * APITCH)           // per region
#define GEMM1_DSMEM (2 * CHUNK_UINT2 * 8)    // 67584 bytes

__device__ __forceinline__ uint32_t pkbf(float a, float b) {
    __nv_bfloat162 t;
    t.x = __float2bfloat16_rn(a);
    t.y = __float2bfloat16_rn(b);
    return *(uint32_t*)&t;
}

__device__ __forceinline__ void mma_bf16(float* c, uint32_t a0, uint32_t a1,
                                         uint32_t a2, uint32_t a3,
                                         uint32_t b0, uint32_t b1) {
    asm volatile(
        "mma.sync.aligned.m16n8k16.row.col.f32.bf16.bf16.f32 "
        "{%0,%1,%2,%3}, {%4,%5,%6,%7}, {%8,%9}, {%0,%1,%2,%3};"
        : "+f"(c[0]), "+f"(c[1]), "+f"(c[2]), "+f"(c[3])
        : "r"(a0), "r"(a1), "r"(a2), "r"(a3), "r"(b0), "r"(b1));
}

__global__ __launch_bounds__(256, 1) void k_gemm1_mma(const float* __restrict__ X,
                                                      const float* __restrict__ Bias,
                                                      const float* __restrict__ attL,
                                                      const float* __restrict__ attR,
                                                      float* __restrict__ al_out,
                                                      float* __restrict__ ar_out,
                                                      float* __restrict__ O, int M) {
    extern __shared__ uint2 sm[];
    uint2* smA = sm;
    uint2* smW = sm + CHUNK_UINT2;
    __shared__ float sBias[128], sAtl[128], sAtr[128];

    const int tid = threadIdx.x;
    const int wt = tid >> 5;          // warp 0..7 -> m-subtile
    const int lane = tid & 31;
    const int r = lane >> 2;          // 0..7
    const int q = lane & 3;           // 0..3
    const int m0 = blockIdx.x * 128;

    if (tid < 128) {
        sBias[tid] = Bias[tid];
        sAtl[tid] = attL[tid];
        sAtr[tid] = attR[tid];
    }

    // staging thread map: row = tid>>1 (0..127), half = tid&1 (k sub-range of 32)
    const int srow = tid >> 1;
    const int shalf = tid & 1;
    int gm = m0 + srow;
    if (gm >= M) gm = M - 1;
    const float* xrow = X + (size_t)gm * IN_DIM + shalf * 32;
    const __nv_bfloat16* whrow = g_wh + (size_t)srow * IN_DIM + shalf * 32;
    const __nv_bfloat16* wlrow = g_wl + (size_t)srow * IN_DIM + shalf * 32;
    uint2* sa = smA + srow * APITCH + shalf * 16;
    uint2* sw = smW + srow * APITCH + shalf * 16;

    float acc[16][4];
#pragma unroll
    for (int i = 0; i < 16; i++)
#pragma unroll
        for (int j = 0; j < 4; j++) acc[i][j] = 0.f;

    for (int c = 0; c < IN_DIM / 64; c++) {
        const int kc = c * 64;
        // stage A: 32 floats -> 16 interleaved uint2
#pragma unroll
        for (int g = 0; g < 8; g++) {
            float4 v = *(const float4*)(xrow + kc + g * 4);
            float h0 = __bfloat162float(__float2bfloat16_rn(v.x));
            float h1 = __bfloat162float(__float2bfloat16_rn(v.y));
            float h2 = __bfloat162float(__float2bfloat16_rn(v.z));
            float h3 = __bfloat162float(__float2bfloat16_rn(v.w));
            uint2 p0, p1;
            p0.x = pkbf(v.x, v.y);
            p0.y = pkbf(v.x - h0, v.y - h1);
            p1.x = pkbf(v.z, v.w);
            p1.y = pkbf(v.z - h2, v.w - h3);
            sa[g * 2 + 0] = p0;
            sa[g * 2 + 1] = p1;
        }
        // stage W: 32 bf16 hi + 32 lo -> 16 interleaved uint2
#pragma unroll
        for (int g = 0; g < 4; g++) {
            uint4 hv = *(const uint4*)(whrow + kc + g * 8);
            uint4 lv = *(const uint4*)(wlrow + kc + g * 8);
            sw[g * 4 + 0] = make_uint2(hv.x, lv.x);
            sw[g * 4 + 1] = make_uint2(hv.y, lv.y);
            sw[g * 4 + 2] = make_uint2(hv.z, lv.z);
            sw[g * 4 + 3] = make_uint2(hv.w, lv.w);
        }
        __syncthreads();

#pragma unroll
        for (int k16 = 0; k16 < 4; k16++) {
            const int kp = k16 * 8;
            // A fragments (rows wt*16 + r, wt*16 + r + 8; k-pairs q, q+4)
            uint2 pa0 = smA[(wt * 16 + r) * APITCH + kp + q];
            uint2 pa1 = smA[(wt * 16 + r + 8) * APITCH + kp + q];
            uint2 pa2 = smA[(wt * 16 + r) * APITCH + kp + q + 4];
            uint2 pa3 = smA[(wt * 16 + r + 8) * APITCH + kp + q + 4];
#pragma unroll
            for (int nt = 0; nt < 16; nt++) {
                uint2 pb0 = smW[(nt * 8 + r) * APITCH + kp + q];
                uint2 pb1 = smW[(nt * 8 + r) * APITCH + kp + q + 4];
                mma_bf16(acc[nt], pa0.x, pa1.x, pa2.x, pa3.x, pb0.x, pb1.x);  // ah*wh
                mma_bf16(acc[nt], pa0.x, pa1.x, pa2.x, pa3.x, pb0.y, pb1.y);  // ah*wl
                mma_bf16(acc[nt], pa0.y, pa1.y, pa2.y, pa3.y, pb0.x, pb1.x);  // al*wh
            }
        }
        __syncthreads();
    }

    // epilogue: rows mlo = m0 + wt*16 + r, mhi = mlo + 8; cols nt*8 + q*2 + {0,1}
    int mlo = m0 + wt * 16 + r;
    int mhi = mlo + 8;
    float slLo = 0.f, srLo = 0.f, slHi = 0.f, srHi = 0.f;
#pragma unroll
    for (int nt = 0; nt < 16; nt++) {
        int c0 = nt * 8 + q * 2;
        float b0 = sBias[c0], b1 = sBias[c0 + 1];
        float l0 = sAtl[c0], l1 = sAtl[c0 + 1];
        float t0 = sAtr[c0], t1 = sAtr[c0 + 1];
        float v0 = fmaxf(acc[nt][0] + b0, 0.f);
        float v1 = fmaxf(acc[nt][1] + b1, 0.f);
        float v2 = fmaxf(acc[nt][2] + b0, 0.f);
        float v3 = fmaxf(acc[nt][3] + b1, 0.f);
        slLo = fmaf(v0, l0, fmaf(v1, l1, slLo));
        srLo = fmaf(v0, t0, fmaf(v1, t1, srLo));
        slHi = fmaf(v2, l0, fmaf(v3, l1, slHi));
        srHi = fmaf(v2, t0, fmaf(v3, t1, srHi));
        if (mlo < M) *(float2*)(O + (size_t)mlo * HIDDEN + c0) = make_float2(v0, v1);
        if (mhi < M) *(float2*)(O + (size_t)mhi * HIDDEN + c0) = make_float2(v2, v3);
    }
#pragma unroll
    for (int o = 1; o <= 2; o <<= 1) {
        slLo += __shfl_xor_sync(0xffffffffu, slLo, o);
        srLo += __shfl_xor_sync(0xffffffffu, srLo, o);
        slHi += __shfl_xor_sync(0xffffffffu, slHi, o);
        srHi += __shfl_xor_sync(0xffffffffu, srHi, o);
    }
    if (q == 0) {
        if (mlo < M) { al_out[mlo] = slLo; ar_out[mlo] = srLo; }
        if (mhi < M) { al_out[mhi] = slHi; ar_out[mhi] = srHi; }
    }
}

// ---------------- aggregation: warp-per-node CSR gather (R4 simple loop) ----------------
__global__ __launch_bounds__(256) void k_gather(const float4* __restrict__ h4,
                                                const float4* __restrict__ raw4,
                                                float4* __restrict__ o4,
                                                const float* __restrict__ al_in,
                                                const float* __restrict__ ar_in,
                                                const float4* __restrict__ attl_next,
                                                const float4* __restrict__ attr_next,
                                                float* __restrict__ al_out,
                                                float* __restrict__ ar_out,
                                                int M) {
    int w = (blockIdx.x * blockDim.x + threadIdx.x) >> 5;
    int lane = threadIdx.x & 31;
    if (w >= M) return;
    int b = g_off[w];
    int e = g_off[w + 1];
    float ar_w = ar_in[w];
    float4 r = raw4[(size_t)w * 32 + lane];
    float4 acc;
    acc.x = EPS * r.x; acc.y = EPS * r.y; acc.z = EPS * r.z; acc.w = EPS * r.w;

    for (int j0 = b; j0 < e; j0 += 32) {
        int jj = j0 + lane;
        float cl = 0.f;
        int sl = 0;
        if (jj < e) {
            sl = __ldg(&g_csr_src[jj]);
            float nrm = __ldg(&g_norm[jj]);
            cl = tanhf(al_in[sl] + ar_w) * nrm;
        }
        int cnt = min(32, e - j0);
        for (int k = 0; k < cnt; k++) {
            float c = __shfl_sync(0xffffffffu, cl, k);
            int s = __shfl_sync(0xffffffffu, sl, k);
            float4 v = h4[(size_t)s * 32 + lane];
            acc.x = fmaf(c, v.x, acc.x);
            acc.y = fmaf(c, v.y, acc.y);
            acc.z = fmaf(c, v.z, acc.z);
            acc.w = fmaf(c, v.w, acc.w);
        }
    }
    o4[(size_t)w * 32 + lane] = acc;

    if (attl_next) {
        float4 wl = attl_next[lane];
        float4 wr = attr_next[lane];
        float a = acc.x * wl.x + acc.y * wl.y + acc.z * wl.z + acc.w * wl.w;
        float bb = acc.x * wr.x + acc.y * wr.y + acc.z * wr.z + acc.w * wr.w;
#pragma unroll
        for (int o = 16; o > 0; o >>= 1) {
            a += __shfl_xor_sync(0xffffffffu, a, o);
            bb += __shfl_xor_sync(0xffffffffu, bb, o);
        }
        if (lane == 0) { al_out[w] = a; ar_out[w] = bb; }
    }
}

// ---------------- GEMM2 + fused log_softmax ----------------
__global__ __launch_bounds__(256) void k_gemm2(const float* __restrict__ H,
                                               const float* __restrict__ W,
                                               const float* __restrict__ B,
                                               float* __restrict__ Emb,
                                               float* __restrict__ Ls, int M) {
    __shared__ float As[16][64];
    __shared__ float Bs[16][64];
    const int tid = threadIdx.x;
    const int m0 = blockIdx.x * 64;
    const int lr = tid >> 2;
    const int lk = (tid & 3) * 4;
    const int tm = (tid >> 4) * 4;
    const int tn = (tid & 15) * 4;

    int gm = m0 + lr;
    if (gm >= M) gm = M - 1;
    const float* hp = H + (size_t)gm * HIDDEN + lk;
    const float* wp = W + (size_t)lr * HIDDEN + lk;

    float acc[4][4];
#pragma unroll
    for (int i = 0; i < 4; i++)
#pragma unroll
        for (int j = 0; j < 4; j++) acc[i][j] = 0.f;

    for (int k0 = 0; k0 < HIDDEN; k0 += 16) {
        float4 xa = *(const float4*)(hp + k0);
        float4 wa = *(const float4*)(wp + k0);
        As[lk + 0][lr] = xa.x; As[lk + 1][lr] = xa.y;
        As[lk + 2][lr] = xa.z; As[lk + 3][lr] = xa.w;
        Bs[lk + 0][lr] = wa.x; Bs[lk + 1][lr] = wa.y;
        Bs[lk + 2][lr] = wa.z; Bs[lk + 3][lr] = wa.w;
        __syncthreads();
#pragma unroll
        for (int kk = 0; kk < 16; kk++) {
            float4 a4 = *(const float4*)&As[kk][tm];
            float4 b4 = *(const float4*)&Bs[kk][tn];
            float a[4] = {a4.x, a4.y, a4.z, a4.w};
            float b[4] = {b4.x, b4.y, b4.z, b4.w};
#pragma unroll
            for (int i = 0; i < 4; i++)
#pragma unroll
                for (int j = 0; j < 4; j++) acc[i][j] = fmaf(a[i], b[j], acc[i][j]);
        }
        __syncthreads();
    }

    float bias[4];
#pragma unroll
    for (int j = 0; j < 4; j++) bias[j] = B[tn + j];

#pragma unroll
    for (int i = 0; i < 4; i++) {
        int m = m0 + tm + i;
        float v[4];
#pragma unroll
        for (int j = 0; j < 4; j++) v[j] = acc[i][j] + bias[j];
        float mx = fmaxf(fmaxf(v[0], v[1]), fmaxf(v[2], v[3]));
#pragma unroll
        for (int o = 8; o > 0; o >>= 1) mx = fmaxf(mx, __shfl_xor_sync(0xffffffffu, mx, o));
        float s = expf(v[0] - mx) + expf(v[1] - mx) + expf(v[2] - mx) + expf(v[3] - mx);
#pragma unroll
        for (int o = 8; o > 0; o >>= 1) s += __shfl_xor_sync(0xffffffffu, s, o);
        float lse = mx + logf(s);
        if (m < M) {
            *(float4*)(Emb + (size_t)m * OUT_DIM + tn) = make_float4(v[0], v[1], v[2], v[3]);
            *(float4*)(Ls + (size_t)m * OUT_DIM + tn) =
                make_float4(v[0] - lse, v[1] - lse, v[2] - lse, v[3] - lse);
        }
    }
}

// ---------------- launch ----------------
extern "C" void kernel_launch(void* const* d_in, const int* in_sizes, int n_in,
                              void* d_out, int out_size) {
    const float* x    = (const float*)d_in[0];
    const int*   ei   = (const int*)  d_in[1];
    const float* t1w  = (const float*)d_in[2];
    const float* t1b  = (const float*)d_in[3];
    const float* t2w  = (const float*)d_in[4];
    const float* t2b  = (const float*)d_in[5];
    const float* attl = (const float*)d_in[6];
    const float* attr = (const float*)d_in[7];

    const int M = in_sizes[0] / IN_DIM;   // 50000
    const int E = in_sizes[1] / 2;        // 600000
    const int* src = ei;
    const int* dst = ei + E;

    float *raw, *hA, *hB, *alA, *arA, *alB, *arB;
    cudaGetSymbolAddress((void**)&raw, g_raw);
    cudaGetSymbolAddress((void**)&hA, g_hA);
    cudaGetSymbolAddress((void**)&hB, g_hB);
    cudaGetSymbolAddress((void**)&alA, g_alA);
    cudaGetSymbolAddress((void**)&arA, g_arA);
    cudaGetSymbolAddress((void**)&alB, g_alB);
    cudaGetSymbolAddress((void**)&arB, g_arB);

    float* out_ls  = (float*)d_out;
    float* out_emb = out_ls + (size_t)M * OUT_DIM;

    cudaFuncSetAttribute(k_gemm1_mma, cudaFuncAttributeMaxDynamicSharedMemorySize,
                         GEMM1_DSMEM);

    static cudaStream_t s2 = nullptr;
    static cudaEvent_t evFork = nullptr, evJoin = nullptr;
    if (!s2) {
        cudaStreamCreateWithFlags(&s2, cudaStreamNonBlocking);
        cudaEventCreateWithFlags(&evFork, cudaEventDisableTiming);
        cudaEventCreateWithFlags(&evJoin, cudaEventDisableTiming);
    }

    // fork: CSR build on s2; W-split + GEMM1 on main stream
    cudaEventRecord(evFork, 0);
    cudaStreamWaitEvent(s2, evFork, 0);

    k_zero_cnt<<<(NN + 255) / 256, 256, 0, s2>>>();
    k_count<<<(E + 255) / 256, 256, 0, s2>>>(dst, E);
    k_scan<<<1, 1024, 0, s2>>>();
    k_fill<<<(E + 255) / 256, 256, 0, s2>>>(src, dst, E);
    cudaEventRecord(evJoin, s2);

    k_wconv<<<(HIDDEN * IN_DIM + 255) / 256, 256>>>(t1w);
    k_gemm1_mma<<<(M + 127) / 128, 256, GEMM1_DSMEM>>>(x, t1b, attl, attr, alA, arA, raw, M);

    cudaStreamWaitEvent(0, evJoin, 0);

    const float* cur = raw;
    float* nxt = hA;
    for (int l = 0; l < N_LAYERS; l++) {
        const float* anl = (l + 1 < N_LAYERS) ? (attl + (l + 1) * HIDDEN) : nullptr;
        const float* anr = (l + 1 < N_LAYERS) ? (attr + (l + 1) * HIDDEN) : nullptr;
        const float* al_in = (l & 1) ? alB : alA;
        const float* ar_in = (l & 1) ? arB : arA;
        float* al_out = (l & 1) ? alA : alB;
        float* ar_out = (l & 1) ? arA : arB;
        k_gather<<<((size_t)M * 32 + 255) / 256, 256>>>((const float4*)cur,
                                                        (const float4*)raw,
                                                        (float4*)nxt,
                                                        al_in, ar_in,
                                                        (const float4*)anl,
                                                        (const float4*)anr,
                                                        al_out, ar_out, M);
        cur = nxt;
        nxt = (cur == hA) ? hB : hA;
    }

    k_gemm2<<<(M + 63) / 64, 256>>>(cur, t2w, t2b, out_emb, out_ls, M);
}

// round 9
// speedup vs baseline: 2.4282x; 1.2748x over previous
#include <cuda_runtime.h>
#include <cuda_bf16.h>
#include <math.h>
#include <stdint.h>

#define NN 50000
#define NE 600000
#define IN_DIM 512
#define HIDDEN 128
#define OUT_DIM 64
#define N_LAYERS 3
#define EPS 0.1f

// ---------------- scratch (static device globals; no allocation) ----------------
__device__ int   g_cnt[NN];
__device__ int   g_off[NN + 4];
__device__ float g_dinv[NN];
__device__ int   g_csr_src[NE];
__device__ float g_norm[NE];
__device__ float g_alA[NN];
__device__ float g_arA[NN];
__device__ float g_alB[NN];
__device__ float g_arB[NN];
__device__ float g_raw[(size_t)NN * HIDDEN];
__device__ float g_hA[(size_t)NN * HIDDEN];
__device__ float g_hB[(size_t)NN * HIDDEN];
// W pre-split + pre-interleaved to match smem tile layout:
// [chunk][row][kpair] -> uint2{hi_pair, lo_pair}, row pitch 34 (2 pad)
#define APITCH 34
#define CHUNK_U2 (128 * APITCH)               // 4352 uint2 per region
__device__ uint2 g_wsplit[8 * CHUNK_U2];

// ---------------- CSR build ----------------
__global__ void k_zero_cnt() {
    int i = blockIdx.x * blockDim.x + threadIdx.x;
    if (i < NN) g_cnt[i] = 0;
}

__global__ void k_count(const int* __restrict__ dst, int E) {
    int e = blockIdx.x * blockDim.x + threadIdx.x;
    if (e < E) atomicAdd(&g_cnt[dst[e]], 1);
}

__global__ __launch_bounds__(1024) void k_scan() {
    __shared__ int sh_warp[32];
    __shared__ int sh_carry;
    const int tid = threadIdx.x, lane = tid & 31, wid = tid >> 5;
    if (tid == 0) sh_carry = 0;
    __syncthreads();
    for (int base = 0; base < NN; base += 4096) {
        int idx = base + tid * 4;
        int4 c = make_int4(0, 0, 0, 0);
        if (idx < NN) c = *(const int4*)&g_cnt[idx];
        int t = c.x + c.y + c.z + c.w;
        int v = t;
#pragma unroll
        for (int o = 1; o < 32; o <<= 1) {
            int tt = __shfl_up_sync(0xffffffffu, v, o);
            if (lane >= o) v += tt;
        }
        if (lane == 31) sh_warp[wid] = v;
        __syncthreads();
        if (wid == 0) {
            int s = sh_warp[lane];
#pragma unroll
            for (int o = 1; o < 32; o <<= 1) {
                int tt = __shfl_up_sync(0xffffffffu, s, o);
                if (lane >= o) s += tt;
            }
            sh_warp[lane] = s;
        }
        __syncthreads();
        int warpoff = (wid > 0) ? sh_warp[wid - 1] : 0;
        int incl = v + warpoff;
        int excl = incl - t + sh_carry;
        if (idx < NN) {
            int4 off;
            off.x = excl;
            off.y = off.x + c.x;
            off.z = off.y + c.y;
            off.w = off.z + c.z;
            *(int4*)&g_off[idx] = off;
            float4 dv;
            dv.x = c.x ? rsqrtf((float)c.x) : 0.f;
            dv.y = c.y ? rsqrtf((float)c.y) : 0.f;
            dv.z = c.z ? rsqrtf((float)c.z) : 0.f;
            dv.w = c.w ? rsqrtf((float)c.w) : 0.f;
            *(float4*)&g_dinv[idx] = dv;
            *(int4*)&g_cnt[idx] = make_int4(0, 0, 0, 0);
        }
        __syncthreads();
        if (tid == 1023) sh_carry += incl;
        __syncthreads();
    }
    if (tid == 0) g_off[NN] = sh_carry;
}

__global__ void k_fill(const int* __restrict__ src, const int* __restrict__ dst, int E) {
    int e = blockIdx.x * blockDim.x + threadIdx.x;
    if (e < E) {
        int s = src[e], d = dst[e];
        int pos = g_off[d] + atomicAdd(&g_cnt[d], 1);
        g_csr_src[pos] = s;
        g_norm[pos] = g_dinv[s] * g_dinv[d];
    }
}

// ---------------- W split + interleave ----------------
__device__ __forceinline__ uint32_t pkbf(float a, float b) {
    __nv_bfloat162 t;
    t.x = __float2bfloat16_rn(a);
    t.y = __float2bfloat16_rn(b);
    return *(uint32_t*)&t;
}

__global__ void k_wconv(const float* __restrict__ W) {
    int i = blockIdx.x * blockDim.x + threadIdx.x;   // over 128*256 kpairs
    if (i >= HIDDEN * 256) return;
    int m = i >> 8;
    int pg = i & 255;
    int c = pg >> 5;
    int p = pg & 31;
    float w0 = W[m * IN_DIM + c * 64 + 2 * p];
    float w1 = W[m * IN_DIM + c * 64 + 2 * p + 1];
    float h0 = __bfloat162float(__float2bfloat16_rn(w0));
    float h1 = __bfloat162float(__float2bfloat16_rn(w1));
    uint2 v;
    v.x = pkbf(w0, w1);
    v.y = pkbf(w0 - h0, w1 - h1);
    g_wsplit[(size_t)c * CHUNK_U2 + m * APITCH + p] = v;
}

// ---------------- GEMM1 via mma.sync bf16-split, cp.async W, occupancy-2 ----------------
#define GEMM1_DSMEM (2 * CHUNK_U2 * 8)   // 69632 bytes (A + W regions)

__device__ __forceinline__ void mma_bf16(float* c, uint32_t a0, uint32_t a1,
                                         uint32_t a2, uint32_t a3,
                                         uint32_t b0, uint32_t b1) {
    asm volatile(
        "mma.sync.aligned.m16n8k16.row.col.f32.bf16.bf16.f32 "
        "{%0,%1,%2,%3}, {%4,%5,%6,%7}, {%8,%9}, {%0,%1,%2,%3};"
        : "+f"(c[0]), "+f"(c[1]), "+f"(c[2]), "+f"(c[3])
        : "r"(a0), "r"(a1), "r"(a2), "r"(a3), "r"(b0), "r"(b1));
}

__global__ __launch_bounds__(256, 2) void k_gemm1_mma(const float* __restrict__ X,
                                                      const float* __restrict__ Bias,
                                                      const float* __restrict__ attL,
                                                      const float* __restrict__ attR,
                                                      float* __restrict__ al_out,
                                                      float* __restrict__ ar_out,
                                                      float* __restrict__ O, int M) {
    extern __shared__ uint2 sm[];
    uint2* smA = sm;
    uint2* smW = sm + CHUNK_U2;
    __shared__ float sBias[128], sAtl[128], sAtr[128];

    const int tid = threadIdx.x;
    const int wt = tid >> 5;
    const int lane = tid & 31;
    const int r = lane >> 2;
    const int q = lane & 3;
    const int m0 = blockIdx.x * 128;

    uint32_t smW_u32;
    asm("{ .reg .u64 t; cvta.to.shared.u64 t, %1; cvt.u32.u64 %0, t; }"
        : "=r"(smW_u32) : "l"((void*)smW));

    if (tid < 128) {
        sBias[tid] = Bias[tid];
        sAtl[tid] = attL[tid];
        sAtr[tid] = attR[tid];
    }

    const int srow = tid >> 1;
    const int shalf = tid & 1;
    int gm = m0 + srow;
    if (gm >= M) gm = M - 1;
    const float* xrow = X + (size_t)gm * IN_DIM + shalf * 32;
    uint2* sa = smA + srow * APITCH + shalf * 16;

    float acc[16][4];
#pragma unroll
    for (int i = 0; i < 16; i++)
#pragma unroll
        for (int j = 0; j < 4; j++) acc[i][j] = 0.f;

    // kick W(0)
    {
        const uint2* gW = g_wsplit;
        for (int i = tid; i < 2176; i += 256)
            asm volatile("cp.async.cg.shared.global [%0], [%1], 16;"
                         :: "r"(smW_u32 + i * 16), "l"(gW + (size_t)i * 2));
        asm volatile("cp.async.commit_group;" ::: "memory");
    }

    for (int c = 0; c < IN_DIM / 64; c++) {
        const int kc = c * 64;
        // stage A: 32 floats -> 16 interleaved uint2 (hi pair, lo pair)
#pragma unroll
        for (int g = 0; g < 8; g++) {
            float4 v = *(const float4*)(xrow + kc + g * 4);
            float h0 = __bfloat162float(__float2bfloat16_rn(v.x));
            float h1 = __bfloat162float(__float2bfloat16_rn(v.y));
            float h2 = __bfloat162float(__float2bfloat16_rn(v.z));
            float h3 = __bfloat162float(__float2bfloat16_rn(v.w));
            uint2 p0, p1;
            p0.x = pkbf(v.x, v.y);
            p0.y = pkbf(v.x - h0, v.y - h1);
            p1.x = pkbf(v.z, v.w);
            p1.y = pkbf(v.z - h2, v.w - h3);
            sa[g * 2 + 0] = p0;
            sa[g * 2 + 1] = p1;
        }
        asm volatile("cp.async.wait_group 0;" ::: "memory");
        __syncthreads();

#pragma unroll
        for (int k16 = 0; k16 < 4; k16++) {
            const int kp = k16 * 8;
            uint2 pa0 = smA[(wt * 16 + r) * APITCH + kp + q];
            uint2 pa1 = smA[(wt * 16 + r + 8) * APITCH + kp + q];
            uint2 pa2 = smA[(wt * 16 + r) * APITCH + kp + q + 4];
            uint2 pa3 = smA[(wt * 16 + r + 8) * APITCH + kp + q + 4];
#pragma unroll
            for (int nt = 0; nt < 16; nt++) {
                uint2 pb0 = smW[(nt * 8 + r) * APITCH + kp + q];
                uint2 pb1 = smW[(nt * 8 + r) * APITCH + kp + q + 4];
                mma_bf16(acc[nt], pa0.x, pa1.x, pa2.x, pa3.x, pb0.x, pb1.x);  // ah*wh
                mma_bf16(acc[nt], pa0.x, pa1.x, pa2.x, pa3.x, pb0.y, pb1.y);  // ah*wl
                mma_bf16(acc[nt], pa0.y, pa1.y, pa2.y, pa3.y, pb0.x, pb1.x);  // al*wh
            }
        }
        __syncthreads();
        if (c + 1 < IN_DIM / 64) {
            const uint2* gW = g_wsplit + (size_t)(c + 1) * CHUNK_U2;
            for (int i = tid; i < 2176; i += 256)
                asm volatile("cp.async.cg.shared.global [%0], [%1], 16;"
                             :: "r"(smW_u32 + i * 16), "l"(gW + (size_t)i * 2));
            asm volatile("cp.async.commit_group;" ::: "memory");
        }
    }

    // epilogue: rows mlo/mhi; cols nt*8 + q*2 + {0,1}
    int mlo = m0 + wt * 16 + r;
    int mhi = mlo + 8;
    float slLo = 0.f, srLo = 0.f, slHi = 0.f, srHi = 0.f;
#pragma unroll
    for (int nt = 0; nt < 16; nt++) {
        int c0 = nt * 8 + q * 2;
        float b0 = sBias[c0], b1 = sBias[c0 + 1];
        float l0 = sAtl[c0], l1 = sAtl[c0 + 1];
        float t0 = sAtr[c0], t1 = sAtr[c0 + 1];
        float v0 = fmaxf(acc[nt][0] + b0, 0.f);
        float v1 = fmaxf(acc[nt][1] + b1, 0.f);
        float v2 = fmaxf(acc[nt][2] + b0, 0.f);
        float v3 = fmaxf(acc[nt][3] + b1, 0.f);
        slLo = fmaf(v0, l0, fmaf(v1, l1, slLo));
        srLo = fmaf(v0, t0, fmaf(v1, t1, srLo));
        slHi = fmaf(v2, l0, fmaf(v3, l1, slHi));
        srHi = fmaf(v2, t0, fmaf(v3, t1, srHi));
        if (mlo < M) *(float2*)(O + (size_t)mlo * HIDDEN + c0) = make_float2(v0, v1);
        if (mhi < M) *(float2*)(O + (size_t)mhi * HIDDEN + c0) = make_float2(v2, v3);
    }
#pragma unroll
    for (int o = 1; o <= 2; o <<= 1) {
        slLo += __shfl_xor_sync(0xffffffffu, slLo, o);
        srLo += __shfl_xor_sync(0xffffffffu, srLo, o);
        slHi += __shfl_xor_sync(0xffffffffu, slHi, o);
        srHi += __shfl_xor_sync(0xffffffffu, srHi, o);
    }
    if (q == 0) {
        if (mlo < M) { al_out[mlo] = slLo; ar_out[mlo] = srLo; }
        if (mhi < M) { al_out[mhi] = slHi; ar_out[mhi] = srHi; }
    }
}

// ---------------- aggregation: warp-per-node CSR gather ----------------
__global__ __launch_bounds__(256) void k_gather(const float4* __restrict__ h4,
                                                const float4* __restrict__ raw4,
                                                float4* __restrict__ o4,
                                                const float* __restrict__ al_in,
                                                const float* __restrict__ ar_in,
                                                const float4* __restrict__ attl_next,
                                                const float4* __restrict__ attr_next,
                                                float* __restrict__ al_out,
                                                float* __restrict__ ar_out,
                                                int M) {
    int w = (blockIdx.x * blockDim.x + threadIdx.x) >> 5;
    int lane = threadIdx.x & 31;
    if (w >= M) return;
    int b = g_off[w];
    int e = g_off[w + 1];
    float ar_w = ar_in[w];
    float4 r = raw4[(size_t)w * 32 + lane];
    float4 acc;
    acc.x = EPS * r.x; acc.y = EPS * r.y; acc.z = EPS * r.z; acc.w = EPS * r.w;

    for (int j0 = b; j0 < e; j0 += 32) {
        int jj = j0 + lane;
        float cl = 0.f;
        int sl = 0;
        if (jj < e) {
            sl = __ldg(&g_csr_src[jj]);
            float nrm = __ldg(&g_norm[jj]);
            cl = tanhf(al_in[sl] + ar_w) * nrm;
        }
        int cnt = min(32, e - j0);
        for (int k = 0; k < cnt; k++) {
            float c = __shfl_sync(0xffffffffu, cl, k);
            int s = __shfl_sync(0xffffffffu, sl, k);
            float4 v = h4[(size_t)s * 32 + lane];
            acc.x = fmaf(c, v.x, acc.x);
            acc.y = fmaf(c, v.y, acc.y);
            acc.z = fmaf(c, v.z, acc.z);
            acc.w = fmaf(c, v.w, acc.w);
        }
    }
    o4[(size_t)w * 32 + lane] = acc;

    if (attl_next) {
        float4 wl = attl_next[lane];
        float4 wr = attr_next[lane];
        float a = acc.x * wl.x + acc.y * wl.y + acc.z * wl.z + acc.w * wl.w;
        float bb = acc.x * wr.x + acc.y * wr.y + acc.z * wr.z + acc.w * wr.w;
#pragma unroll
        for (int o = 16; o > 0; o >>= 1) {
            a += __shfl_xor_sync(0xffffffffu, a, o);
            bb += __shfl_xor_sync(0xffffffffu, bb, o);
        }
        if (lane == 0) { al_out[w] = a; ar_out[w] = bb; }
    }
}

// ---------------- GEMM2 + fused log_softmax ----------------
__global__ __launch_bounds__(256) void k_gemm2(const float* __restrict__ H,
                                               const float* __restrict__ W,
                                               const float* __restrict__ B,
                                               float* __restrict__ Emb,
                                               float* __restrict__ Ls, int M) {
    __shared__ float As[16][64];
    __shared__ float Bs[16][64];
    const int tid = threadIdx.x;
    const int m0 = blockIdx.x * 64;
    const int lr = tid >> 2;
    const int lk = (tid & 3) * 4;
    const int tm = (tid >> 4) * 4;
    const int tn = (tid & 15) * 4;

    int gm = m0 + lr;
    if (gm >= M) gm = M - 1;
    const float* hp = H + (size_t)gm * HIDDEN + lk;
    const float* wp = W + (size_t)lr * HIDDEN + lk;

    float acc[4][4];
#pragma unroll
    for (int i = 0; i < 4; i++)
#pragma unroll
        for (int j = 0; j < 4; j++) acc[i][j] = 0.f;

    for (int k0 = 0; k0 < HIDDEN; k0 += 16) {
        float4 xa = *(const float4*)(hp + k0);
        float4 wa = *(const float4*)(wp + k0);
        As[lk + 0][lr] = xa.x; As[lk + 1][lr] = xa.y;
        As[lk + 2][lr] = xa.z; As[lk + 3][lr] = xa.w;
        Bs[lk + 0][lr] = wa.x; Bs[lk + 1][lr] = wa.y;
        Bs[lk + 2][lr] = wa.z; Bs[lk + 3][lr] = wa.w;
        __syncthreads();
#pragma unroll
        for (int kk = 0; kk < 16; kk++) {
            float4 a4 = *(const float4*)&As[kk][tm];
            float4 b4 = *(const float4*)&Bs[kk][tn];
            float a[4] = {a4.x, a4.y, a4.z, a4.w};
            float b[4] = {b4.x, b4.y, b4.z, b4.w};
#pragma unroll
            for (int i = 0; i < 4; i++)
#pragma unroll
                for (int j = 0; j < 4; j++) acc[i][j] = fmaf(a[i], b[j], acc[i][j]);
        }
        __syncthreads();
    }

    float bias[4];
#pragma unroll
    for (int j = 0; j < 4; j++) bias[j] = B[tn + j];

#pragma unroll
    for (int i = 0; i < 4; i++) {
        int m = m0 + tm + i;
        float v[4];
#pragma unroll
        for (int j = 0; j < 4; j++) v[j] = acc[i][j] + bias[j];
        float mx = fmaxf(fmaxf(v[0], v[1]), fmaxf(v[2], v[3]));
#pragma unroll
        for (int o = 8; o > 0; o >>= 1) mx = fmaxf(mx, __shfl_xor_sync(0xffffffffu, mx, o));
        float s = expf(v[0] - mx) + expf(v[1] - mx) + expf(v[2] - mx) + expf(v[3] - mx);
#pragma unroll
        for (int o = 8; o > 0; o >>= 1) s += __shfl_xor_sync(0xffffffffu, s, o);
        float lse = mx + logf(s);
        if (m < M) {
            *(float4*)(Emb + (size_t)m * OUT_DIM + tn) = make_float4(v[0], v[1], v[2], v[3]);
            *(float4*)(Ls + (size_t)m * OUT_DIM + tn) =
                make_float4(v[0] - lse, v[1] - lse, v[2] - lse, v[3] - lse);
        }
    }
}

// ---------------- launch ----------------
extern "C" void kernel_launch(void* const* d_in, const int* in_sizes, int n_in,
                              void* d_out, int out_size) {
    const float* x    = (const float*)d_in[0];
    const int*   ei   = (const int*)  d_in[1];
    const float* t1w  = (const float*)d_in[2];
    const float* t1b  = (const float*)d_in[3];
    const float* t2w  = (const float*)d_in[4];
    const float* t2b  = (const float*)d_in[5];
    const float* attl = (const float*)d_in[6];
    const float* attr = (const float*)d_in[7];

    const int M = in_sizes[0] / IN_DIM;   // 50000
    const int E = in_sizes[1] / 2;        // 600000
    const int* src = ei;
    const int* dst = ei + E;

    float *raw, *hA, *hB, *alA, *arA, *alB, *arB;
    cudaGetSymbolAddress((void**)&raw, g_raw);
    cudaGetSymbolAddress((void**)&hA, g_hA);
    cudaGetSymbolAddress((void**)&hB, g_hB);
    cudaGetSymbolAddress((void**)&alA, g_alA);
    cudaGetSymbolAddress((void**)&arA, g_arA);
    cudaGetSymbolAddress((void**)&alB, g_alB);
    cudaGetSymbolAddress((void**)&arB, g_arB);

    float* out_ls  = (float*)d_out;
    float* out_emb = out_ls + (size_t)M * OUT_DIM;

    cudaFuncSetAttribute(k_gemm1_mma, cudaFuncAttributeMaxDynamicSharedMemorySize,
                         GEMM1_DSMEM);

    static cudaStream_t s2 = nullptr;
    static cudaEvent_t evFork = nullptr, evJoin = nullptr;
    if (!s2) {
        cudaStreamCreateWithFlags(&s2, cudaStreamNonBlocking);
        cudaEventCreateWithFlags(&evFork, cudaEventDisableTiming);
        cudaEventCreateWithFlags(&evJoin, cudaEventDisableTiming);
    }

    // fork: CSR build on s2; W-split + GEMM1 on main stream
    cudaEventRecord(evFork, 0);
    cudaStreamWaitEvent(s2, evFork, 0);

    k_zero_cnt<<<(NN + 255) / 256, 256, 0, s2>>>();
    k_count<<<(E + 255) / 256, 256, 0, s2>>>(dst, E);
    k_scan<<<1, 1024, 0, s2>>>();
    k_fill<<<(E + 255) / 256, 256, 0, s2>>>(src, dst, E);
    cudaEventRecord(evJoin, s2);

    k_wconv<<<(HIDDEN * 256 + 255) / 256, 256>>>(t1w);
    k_gemm1_mma<<<(M + 127) / 128, 256, GEMM1_DSMEM>>>(x, t1b, attl, attr, alA, arA, raw, M);

    cudaStreamWaitEvent(0, evJoin, 0);

    const float* cur = raw;
    float* nxt = hA;
    for (int l = 0; l < N_LAYERS; l++) {
        const float* anl = (l + 1 < N_LAYERS) ? (attl + (l + 1) * HIDDEN) : nullptr;
        const float* anr = (l + 1 < N_LAYERS) ? (attr + (l + 1) * HIDDEN) : nullptr;
        const float* al_in = (l & 1) ? alB : alA;
        const float* ar_in = (l & 1) ? arB : arA;
        float* al_out = (l & 1) ? alA : alB;
        float* ar_out = (l & 1) ? arA : arB;
        k_gather<<<((size_t)M * 32 + 255) / 256, 256>>>((const float4*)cur,
                                                        (const float4*)raw,
                                                        (float4*)nxt,
                                                        al_in, ar_in,
                                                        (const float4*)anl,
                                                        (const float4*)anr,
                                                        al_out, ar_out, M);
        cur = nxt;
        nxt = (cur == hA) ? hB : hA;
    }

    k_gemm2<<<(M + 63) / 64, 256>>>(cur, t2w, t2b, out_emb, out_ls, M);
}